// round 9
// baseline (speedup 1.0000x reference)
#include <cuda_runtime.h>

#define NN   100000
#define FIN  256
#define HD   8
#define EE   3200000

// ---------------- scratch (device globals; no allocation allowed) -----------
// layer-indexed: [0] = GAT layer 1, [1] = GAT layer 2
__device__ float4 g_h[2][NN * 2];     // h[n] as 2x float4 (8 floats per node)
__device__ float  g_as[2][NN];        // a_src per node
__device__ float  g_ad[2][NN];        // a_dst per node
__device__ float4 g_num[2][NN * 2];   // softmax numerator accumulator (8 floats)
__device__ float  g_den[2][NN];       // softmax denominator accumulator

__device__ __forceinline__ float leaky02(float v) {
    return v >= 0.f ? v : 0.2f * v;
}

__device__ __forceinline__ void red_add_v4(float4* p, float a, float b, float c, float d) {
    asm volatile("red.global.add.v4.f32 [%0], {%1,%2,%3,%4};"
                 :: "l"(p), "f"(a), "f"(b), "f"(c), "f"(d) : "memory");
}
__device__ __forceinline__ void red_add_f(float* p, float v) {
    asm volatile("red.global.add.f32 [%0], %1;" :: "l"(p), "f"(v) : "memory");
}

// ---------------------------------------------------------------------------
// Kernel 1: h1 = x @ W1. One warp per node. W1 (256x8 = 8KB) is sliced into
// registers: lane l owns rows {i*128 + 4l + j} (i in 0..1, j in 0..3), so the
// mainloop is pure LDG.128 + FFMA — zero shared-memory traffic. Also computes
// a_s1/a_d1 and the self-loop init of num1/den1.
// ---------------------------------------------------------------------------
__global__ void __launch_bounds__(256, 2)
k_gemm1(const float4* __restrict__ x4, const float* __restrict__ W1,
        const float* __restrict__ att_s, const float* __restrict__ att_d) {
    int tid  = threadIdx.x;
    int warp = tid >> 5, lane = tid & 31;
    int n = blockIdx.x * 8 + warp;

    // Per-lane register slice of W1: w[i][j][k] = W1[(i*128 + lane*4 + j)][k]
    float w[2][4][HD];
    #pragma unroll
    for (int i = 0; i < 2; i++) {
        #pragma unroll
        for (int j = 0; j < 4; j++) {
            const float4* wp = (const float4*)(W1 + (size_t)(i * 128 + lane * 4 + j) * HD);
            float4 wa = wp[0], wb = wp[1];
            w[i][j][0] = wa.x; w[i][j][1] = wa.y; w[i][j][2] = wa.z; w[i][j][3] = wa.w;
            w[i][j][4] = wb.x; w[i][j][5] = wb.y; w[i][j][6] = wb.z; w[i][j][7] = wb.w;
        }
    }

    if (n >= NN) return;

    float acc[HD];
    #pragma unroll
    for (int k = 0; k < HD; k++) acc[k] = 0.f;

    // x row: 256 floats = 64 float4; lane covers index i*32 + lane (i in 0..1)
    #pragma unroll
    for (int i = 0; i < 2; i++) {
        float4 v = x4[(size_t)n * 64 + i * 32 + lane];
        #pragma unroll
        for (int k = 0; k < HD; k++)
            acc[k] += v.x * w[i][0][k] + v.y * w[i][1][k]
                    + v.z * w[i][2][k] + v.w * w[i][3][k];
    }

    // butterfly reduce: lane 0 ends with full sums
    #pragma unroll
    for (int off = 16; off; off >>= 1) {
        #pragma unroll
        for (int k = 0; k < HD; k++)
            acc[k] += __shfl_xor_sync(0xffffffffu, acc[k], off);
    }

    if (lane == 0) {
        float as = 0.f, ad = 0.f;
        #pragma unroll
        for (int k = 0; k < HD; k++) { as += acc[k] * att_s[k]; ad += acc[k] * att_d[k]; }
        float ex = __expf(leaky02(as + ad));   // self-loop edge weight
        g_as[0][n] = as;
        g_ad[0][n] = ad;
        g_den[0][n] = ex;
        g_h[0][2 * n]     = make_float4(acc[0], acc[1], acc[2], acc[3]);
        g_h[0][2 * n + 1] = make_float4(acc[4], acc[5], acc[6], acc[7]);
        g_num[0][2 * n]     = make_float4(ex * acc[0], ex * acc[1], ex * acc[2], ex * acc[3]);
        g_num[0][2 * n + 1] = make_float4(ex * acc[4], ex * acc[5], ex * acc[6], ex * acc[7]);
    }
}

// ---------------------------------------------------------------------------
// Edge pass (shared by both layers): TWO edges per thread via int2 index loads
// (edge_index is int32 on device — JAX x64-disabled coerces int64 to int32).
// ex = exp(leaky(a_s[src] + a_d[dst])); num[dst] += ex*h[src]; den[dst] += ex
// (max-centering dropped: |e| <= ~4 here, exp is safe in fp32)
// ---------------------------------------------------------------------------
__global__ void __launch_bounds__(256)
k_edge(const int2* __restrict__ ei_src2, const int2* __restrict__ ei_dst2, int layer) {
    int t = blockIdx.x * blockDim.x + threadIdx.x;   // handles edges 2t, 2t+1
    if (t >= EE / 2) return;
    int2 ss = ei_src2[t];
    int2 dd = ei_dst2[t];

    const float*  pas = g_as[layer];
    const float*  pad = g_ad[layer];
    const float4* ph  = g_h[layer];
    float4*       pn  = g_num[layer];
    float*        pd  = g_den[layer];

    // edge 0
    {
        int s = ss.x, d = dd.x;
        float ex = __expf(leaky02(pas[s] + pad[d]));
        float4 h0 = ph[2 * s];
        float4 h1 = ph[2 * s + 1];
        red_add_v4(&pn[2 * d],     ex * h0.x, ex * h0.y, ex * h0.z, ex * h0.w);
        red_add_v4(&pn[2 * d + 1], ex * h1.x, ex * h1.y, ex * h1.z, ex * h1.w);
        red_add_f(&pd[d], ex);
    }
    // edge 1
    {
        int s = ss.y, d = dd.y;
        float ex = __expf(leaky02(pas[s] + pad[d]));
        float4 h0 = ph[2 * s];
        float4 h1 = ph[2 * s + 1];
        red_add_v4(&pn[2 * d],     ex * h0.x, ex * h0.y, ex * h0.z, ex * h0.w);
        red_add_v4(&pn[2 * d + 1], ex * h1.x, ex * h1.y, ex * h1.z, ex * h1.w);
        red_add_f(&pd[d], ex);
    }
}

// ---------------------------------------------------------------------------
// Kernel 3: finish layer 1 (x1 = num/den + b1), layer-2 projection
// h2 = x1 @ W2, a_s2/a_d2, self-loop init of num2/den2. One thread per node.
// ---------------------------------------------------------------------------
__global__ void __launch_bounds__(256)
k_node2(const float* __restrict__ b1, const float* __restrict__ W2,
        const float* __restrict__ att_s, const float* __restrict__ att_d) {
    __shared__ float W2sh[HD * HD];
    __shared__ float b1sh[HD], as_sh[HD], ad_sh[HD];
    int tid = threadIdx.x;
    if (tid < HD * HD) W2sh[tid] = W2[tid];
    if (tid < HD) { b1sh[tid] = b1[tid]; as_sh[tid] = att_s[tid]; ad_sh[tid] = att_d[tid]; }
    __syncthreads();

    int n = blockIdx.x * blockDim.x + tid;
    if (n >= NN) return;

    float inv = 1.f / g_den[0][n];
    float4 n0 = g_num[0][2 * n];
    float4 n1 = g_num[0][2 * n + 1];
    float x1[HD];
    x1[0] = n0.x * inv + b1sh[0]; x1[1] = n0.y * inv + b1sh[1];
    x1[2] = n0.z * inv + b1sh[2]; x1[3] = n0.w * inv + b1sh[3];
    x1[4] = n1.x * inv + b1sh[4]; x1[5] = n1.y * inv + b1sh[5];
    x1[6] = n1.z * inv + b1sh[6]; x1[7] = n1.w * inv + b1sh[7];

    float h2[HD];
    #pragma unroll
    for (int k = 0; k < HD; k++) {
        float acc = 0.f;
        #pragma unroll
        for (int i = 0; i < HD; i++) acc += x1[i] * W2sh[i * HD + k];
        h2[k] = acc;
    }

    float as = 0.f, ad = 0.f;
    #pragma unroll
    for (int k = 0; k < HD; k++) { as += h2[k] * as_sh[k]; ad += h2[k] * ad_sh[k]; }
    float ex = __expf(leaky02(as + ad));   // self-loop

    g_as[1][n] = as;
    g_ad[1][n] = ad;
    g_den[1][n] = ex;
    g_h[1][2 * n]     = make_float4(h2[0], h2[1], h2[2], h2[3]);
    g_h[1][2 * n + 1] = make_float4(h2[4], h2[5], h2[6], h2[7]);
    g_num[1][2 * n]     = make_float4(ex * h2[0], ex * h2[1], ex * h2[2], ex * h2[3]);
    g_num[1][2 * n + 1] = make_float4(ex * h2[4], ex * h2[5], ex * h2[6], ex * h2[7]);
}

// ---------------------------------------------------------------------------
// Kernel 5: finish layer 2 + linear head + LeakyReLU(0.01). One thread/node.
// ---------------------------------------------------------------------------
__global__ void __launch_bounds__(256)
k_out(const float* __restrict__ b2, const float* __restrict__ W_lin,
      const float* __restrict__ b_lin, float* __restrict__ out) {
    __shared__ float b2sh[HD], wl[HD], bl;
    int tid = threadIdx.x;
    if (tid < HD) { b2sh[tid] = b2[tid]; wl[tid] = W_lin[tid]; }
    if (tid == 0) bl = b_lin[0];
    __syncthreads();

    int n = blockIdx.x * blockDim.x + tid;
    if (n >= NN) return;

    float inv = 1.f / g_den[1][n];
    float4 n0 = g_num[1][2 * n];
    float4 n1 = g_num[1][2 * n + 1];

    float v = bl;
    v += (n0.x * inv + b2sh[0]) * wl[0];
    v += (n0.y * inv + b2sh[1]) * wl[1];
    v += (n0.z * inv + b2sh[2]) * wl[2];
    v += (n0.w * inv + b2sh[3]) * wl[3];
    v += (n1.x * inv + b2sh[4]) * wl[4];
    v += (n1.y * inv + b2sh[5]) * wl[5];
    v += (n1.z * inv + b2sh[6]) * wl[6];
    v += (n1.w * inv + b2sh[7]) * wl[7];

    out[n] = v >= 0.f ? v : 0.01f * v;
}

// ---------------------------------------------------------------------------
extern "C" void kernel_launch(void* const* d_in, const int* in_sizes, int n_in,
                              void* d_out, int out_size) {
    // metadata order: x, edge_index(int32!), edge_type, edge_time,
    //                 W1, att_src1, att_dst1, b1, W2, att_src2, att_dst2, b2,
    //                 W_lin, b_lin
    const float* x    = (const float*)d_in[0];
    const int*   ei   = (const int*)d_in[1];
    const float* W1   = (const float*)d_in[4];
    const float* as1  = (const float*)d_in[5];
    const float* ad1  = (const float*)d_in[6];
    const float* b1   = (const float*)d_in[7];
    const float* W2   = (const float*)d_in[8];
    const float* as2  = (const float*)d_in[9];
    const float* ad2  = (const float*)d_in[10];
    const float* b2   = (const float*)d_in[11];
    const float* Wlin = (const float*)d_in[12];
    const float* blin = (const float*)d_in[13];
    float*       out  = (float*)d_out;

    const int TB = 256;
    int grid_gemm1 = (NN + 7) / 8;                 // 8 warps/block, 1 node/warp
    int grid_edges = (EE / 2 + TB - 1) / TB;       // 6250 (2 edges/thread)
    int grid_nodes = (NN + TB - 1) / TB;           // 391

    const int2* ei_src2 = (const int2*)ei;         // first half: src
    const int2* ei_dst2 = (const int2*)(ei + EE);  // second half: dst

    k_gemm1<<<grid_gemm1, TB>>>((const float4*)x, W1, as1, ad1);
    k_edge<<<grid_edges, TB>>>(ei_src2, ei_dst2, 0);
    k_node2<<<grid_nodes, TB>>>(b1, W2, as2, ad2);
    k_edge<<<grid_edges, TB>>>(ei_src2, ei_dst2, 1);
    k_out<<<grid_nodes, TB>>>(b2, Wlin, blin, out);
}

// round 12
// speedup vs baseline: 1.6347x; 1.6347x over previous
#include <cuda_runtime.h>

#define NN    100000
#define FIN   256
#define HD    8
#define EE    3200000
#define NBLK  98          // ceil(NN / 1024) scan blocks

// ---------------- scratch (device globals; no allocation allowed) -----------
__device__ float4 g_h[2][NN * 2];   // h[n] as 2x float4
__device__ float  g_as[2][NN];      // a_src per node
__device__ float  g_ad[2][NN];      // a_dst per node
__device__ int    g_deg[NN];        // in-degree (excl. self-loop)
__device__ int    g_off[NN];        // CSR exclusive offsets
__device__ int    g_cur[NN];        // scatter cursors
__device__ int    g_bsum[NBLK];     // scan block sums
__device__ int    g_csr_src[EE];    // src node per edge, grouped by dst

__device__ __forceinline__ float leaky02(float v) { return v >= 0.f ? v : 0.2f * v; }

// ---------------------------------------------------------------------------
// CSR build: zero -> hist -> block scan -> top scan -> add+cursor -> scatter
// ---------------------------------------------------------------------------
__global__ void __launch_bounds__(256) k_zero() {
    int i = blockIdx.x * 256 + threadIdx.x;
    if (i < NN) g_deg[i] = 0;
}

__global__ void __launch_bounds__(256) k_hist(const int2* __restrict__ ei_dst2) {
    int t = blockIdx.x * 256 + threadIdx.x;
    if (t >= EE / 2) return;
    int2 dd = ei_dst2[t];
    atomicAdd(&g_deg[dd.x], 1);
    atomicAdd(&g_deg[dd.y], 1);
}

__global__ void __launch_bounds__(256) k_scan_block() {
    __shared__ int woff[8];
    int t = threadIdx.x, lane = t & 31, warp = t >> 5;
    int idx = blockIdx.x * 1024 + t * 4;
    int v0 = idx     < NN ? g_deg[idx]     : 0;
    int v1 = idx + 1 < NN ? g_deg[idx + 1] : 0;
    int v2 = idx + 2 < NN ? g_deg[idx + 2] : 0;
    int v3 = idx + 3 < NN ? g_deg[idx + 3] : 0;
    int tsum = v0 + v1 + v2 + v3;

    int incl = tsum;
    #pragma unroll
    for (int o = 1; o < 32; o <<= 1) {
        int u = __shfl_up_sync(0xffffffffu, incl, o);
        if (lane >= o) incl += u;
    }
    if (lane == 31) woff[warp] = incl;
    __syncthreads();
    if (t < 8) {
        int w = woff[t];
        int winc = w;
        #pragma unroll
        for (int o = 1; o < 8; o <<= 1) {
            int u = __shfl_up_sync(0xffu, winc, o);
            if (t >= o) winc += u;
        }
        woff[t] = winc - w;                 // exclusive warp offset
        if (t == 7) g_bsum[blockIdx.x] = winc;  // block total
    }
    __syncthreads();
    int excl = incl - tsum + woff[warp];
    if (idx     < NN) g_off[idx]     = excl;
    if (idx + 1 < NN) g_off[idx + 1] = excl + v0;
    if (idx + 2 < NN) g_off[idx + 2] = excl + v0 + v1;
    if (idx + 3 < NN) g_off[idx + 3] = excl + v0 + v1 + v2;
}

__global__ void __launch_bounds__(128) k_scan_top() {
    __shared__ int s[128];
    int t = threadIdx.x;
    int orig = t < NBLK ? g_bsum[t] : 0;
    s[t] = orig;
    __syncthreads();
    #pragma unroll
    for (int o = 1; o < 128; o <<= 1) {
        int v = 0;
        if (t >= o) v = s[t - o];
        __syncthreads();
        s[t] += v;
        __syncthreads();
    }
    if (t < NBLK) g_bsum[t] = s[t] - orig;  // exclusive
}

__global__ void __launch_bounds__(256) k_scan_add() {
    int i = blockIdx.x * 256 + threadIdx.x;
    if (i < NN) {
        int o = g_off[i] + g_bsum[i >> 10];
        g_off[i] = o;
        g_cur[i] = o;
    }
}

__global__ void __launch_bounds__(256) k_scatter(const int2* __restrict__ ei_src2,
                                                 const int2* __restrict__ ei_dst2) {
    int t = blockIdx.x * 256 + threadIdx.x;
    if (t >= EE / 2) return;
    int2 ss = ei_src2[t];
    int2 dd = ei_dst2[t];
    int p0 = atomicAdd(&g_cur[dd.x], 1);
    g_csr_src[p0] = ss.x;
    int p1 = atomicAdd(&g_cur[dd.y], 1);
    g_csr_src[p1] = ss.y;
}

// ---------------------------------------------------------------------------
// Kernel: h1 = x @ W1. One warp per 16 nodes (W register-slice load amortized).
// Lane l owns W rows {i*128 + 4l + j}; mainloop per node = 2x LDG.128 + FFMA.
// ---------------------------------------------------------------------------
#define GPN 16   // nodes per warp
__global__ void __launch_bounds__(256, 2)
k_gemm1(const float4* __restrict__ x4, const float* __restrict__ W1,
        const float* __restrict__ att_s, const float* __restrict__ att_d) {
    int tid  = threadIdx.x;
    int warp = tid >> 5, lane = tid & 31;
    int wg = blockIdx.x * 8 + warp;       // global warp id
    int n0 = wg * GPN;

    // Per-lane register slice of W1: w[i][j][k] = W1[(i*128 + lane*4 + j)][k]
    float w[2][4][HD];
    #pragma unroll
    for (int i = 0; i < 2; i++) {
        #pragma unroll
        for (int j = 0; j < 4; j++) {
            const float4* wp = (const float4*)(W1 + (size_t)(i * 128 + lane * 4 + j) * HD);
            float4 wa = wp[0], wb = wp[1];
            w[i][j][0] = wa.x; w[i][j][1] = wa.y; w[i][j][2] = wa.z; w[i][j][3] = wa.w;
            w[i][j][4] = wb.x; w[i][j][5] = wb.y; w[i][j][6] = wb.z; w[i][j][7] = wb.w;
        }
    }
    float as_w[HD], ad_w[HD];
    #pragma unroll
    for (int k = 0; k < HD; k++) { as_w[k] = att_s[k]; ad_w[k] = att_d[k]; }

    for (int t = 0; t < GPN; t++) {
        int n = n0 + t;
        if (n >= NN) break;

        float acc[HD];
        #pragma unroll
        for (int k = 0; k < HD; k++) acc[k] = 0.f;

        #pragma unroll
        for (int i = 0; i < 2; i++) {
            float4 v = x4[(size_t)n * 64 + i * 32 + lane];
            #pragma unroll
            for (int k = 0; k < HD; k++)
                acc[k] += v.x * w[i][0][k] + v.y * w[i][1][k]
                        + v.z * w[i][2][k] + v.w * w[i][3][k];
        }
        #pragma unroll
        for (int off = 16; off; off >>= 1) {
            #pragma unroll
            for (int k = 0; k < HD; k++)
                acc[k] += __shfl_xor_sync(0xffffffffu, acc[k], off);
        }
        if (lane == 0) {
            float as = 0.f, ad = 0.f;
            #pragma unroll
            for (int k = 0; k < HD; k++) { as += acc[k] * as_w[k]; ad += acc[k] * ad_w[k]; }
            g_as[0][n] = as;
            g_ad[0][n] = ad;
            g_h[0][2 * n]     = make_float4(acc[0], acc[1], acc[2], acc[3]);
            g_h[0][2 * n + 1] = make_float4(acc[4], acc[5], acc[6], acc[7]);
        }
    }
}

// ---------------------------------------------------------------------------
// Gather layer 1 (atomic-free, CSR) + fused layer-2 projection.
// One thread per dst node: softmax-weighted sum over incoming edges + self-loop,
// then x1 = num/den + b1; h2 = x1 @ W2; a_s2/a_d2.
// ---------------------------------------------------------------------------
__global__ void __launch_bounds__(256)
k_gather1(const float* __restrict__ b1, const float* __restrict__ W2,
          const float* __restrict__ att_s, const float* __restrict__ att_d) {
    __shared__ float W2sh[HD * HD];
    __shared__ float b1sh[HD], as_sh[HD], ad_sh[HD];
    int tid = threadIdx.x;
    if (tid < HD * HD) W2sh[tid] = W2[tid];
    if (tid < HD) { b1sh[tid] = b1[tid]; as_sh[tid] = att_s[tid]; ad_sh[tid] = att_d[tid]; }
    __syncthreads();

    int n = blockIdx.x * 256 + tid;
    if (n >= NN) return;

    float adn = g_ad[0][n];
    float ex  = __expf(leaky02(g_as[0][n] + adn));   // self-loop
    float4 a0 = g_h[0][2 * n];
    float4 a1 = g_h[0][2 * n + 1];
    float num[HD];
    num[0] = ex * a0.x; num[1] = ex * a0.y; num[2] = ex * a0.z; num[3] = ex * a0.w;
    num[4] = ex * a1.x; num[5] = ex * a1.y; num[6] = ex * a1.z; num[7] = ex * a1.w;
    float den = ex;

    int st = g_off[n], dg = g_deg[n];
    for (int j = 0; j < dg; j++) {
        int s = g_csr_src[st + j];
        float e = __expf(leaky02(g_as[0][s] + adn));
        float4 h0 = g_h[0][2 * s];
        float4 h1 = g_h[0][2 * s + 1];
        num[0] += e * h0.x; num[1] += e * h0.y; num[2] += e * h0.z; num[3] += e * h0.w;
        num[4] += e * h1.x; num[5] += e * h1.y; num[6] += e * h1.z; num[7] += e * h1.w;
        den += e;
    }

    float inv = 1.f / den;
    float x1[HD];
    #pragma unroll
    for (int k = 0; k < HD; k++) x1[k] = num[k] * inv + b1sh[k];

    float h2[HD];
    #pragma unroll
    for (int k = 0; k < HD; k++) {
        float acc = 0.f;
        #pragma unroll
        for (int i = 0; i < HD; i++) acc += x1[i] * W2sh[i * HD + k];
        h2[k] = acc;
    }
    float as = 0.f, ad = 0.f;
    #pragma unroll
    for (int k = 0; k < HD; k++) { as += h2[k] * as_sh[k]; ad += h2[k] * ad_sh[k]; }

    g_as[1][n] = as;
    g_ad[1][n] = ad;
    g_h[1][2 * n]     = make_float4(h2[0], h2[1], h2[2], h2[3]);
    g_h[1][2 * n + 1] = make_float4(h2[4], h2[5], h2[6], h2[7]);
}

// ---------------------------------------------------------------------------
// Gather layer 2 + fused linear head + LeakyReLU(0.01).
// ---------------------------------------------------------------------------
__global__ void __launch_bounds__(256)
k_gather2(const float* __restrict__ b2, const float* __restrict__ W_lin,
          const float* __restrict__ b_lin, float* __restrict__ out) {
    __shared__ float b2sh[HD], wl[HD], bl;
    int tid = threadIdx.x;
    if (tid < HD) { b2sh[tid] = b2[tid]; wl[tid] = W_lin[tid]; }
    if (tid == 0) bl = b_lin[0];
    __syncthreads();

    int n = blockIdx.x * 256 + tid;
    if (n >= NN) return;

    float adn = g_ad[1][n];
    float ex  = __expf(leaky02(g_as[1][n] + adn));   // self-loop
    float4 a0 = g_h[1][2 * n];
    float4 a1 = g_h[1][2 * n + 1];
    float num[HD];
    num[0] = ex * a0.x; num[1] = ex * a0.y; num[2] = ex * a0.z; num[3] = ex * a0.w;
    num[4] = ex * a1.x; num[5] = ex * a1.y; num[6] = ex * a1.z; num[7] = ex * a1.w;
    float den = ex;

    int st = g_off[n], dg = g_deg[n];
    for (int j = 0; j < dg; j++) {
        int s = g_csr_src[st + j];
        float e = __expf(leaky02(g_as[1][s] + adn));
        float4 h0 = g_h[1][2 * s];
        float4 h1 = g_h[1][2 * s + 1];
        num[0] += e * h0.x; num[1] += e * h0.y; num[2] += e * h0.z; num[3] += e * h0.w;
        num[4] += e * h1.x; num[5] += e * h1.y; num[6] += e * h1.z; num[7] += e * h1.w;
        den += e;
    }

    float inv = 1.f / den;
    float v = bl;
    #pragma unroll
    for (int k = 0; k < HD; k++) v += (num[k] * inv + b2sh[k]) * wl[k];
    out[n] = v >= 0.f ? v : 0.01f * v;
}

// ---------------------------------------------------------------------------
extern "C" void kernel_launch(void* const* d_in, const int* in_sizes, int n_in,
                              void* d_out, int out_size) {
    // metadata order: x, edge_index(int32), edge_type, edge_time,
    //                 W1, att_src1, att_dst1, b1, W2, att_src2, att_dst2, b2,
    //                 W_lin, b_lin
    const float* x    = (const float*)d_in[0];
    const int*   ei   = (const int*)d_in[1];
    const float* W1   = (const float*)d_in[4];
    const float* as1  = (const float*)d_in[5];
    const float* ad1  = (const float*)d_in[6];
    const float* b1   = (const float*)d_in[7];
    const float* W2   = (const float*)d_in[8];
    const float* as2  = (const float*)d_in[9];
    const float* ad2  = (const float*)d_in[10];
    const float* b2   = (const float*)d_in[11];
    const float* Wlin = (const float*)d_in[12];
    const float* blin = (const float*)d_in[13];
    float*       out  = (float*)d_out;

    const int2* ei_src2 = (const int2*)ei;         // first half: src
    const int2* ei_dst2 = (const int2*)(ei + EE);  // second half: dst

    int grid_nodes = (NN + 255) / 256;             // 391
    int grid_half  = (EE / 2 + 255) / 256;         // 6250
    int grid_gemm1 = (NN + 8 * GPN - 1) / (8 * GPN); // 782

    // CSR build (atomic-free gathers downstream)
    k_zero<<<grid_nodes, 256>>>();
    k_hist<<<grid_half, 256>>>(ei_dst2);
    k_scan_block<<<NBLK, 256>>>();
    k_scan_top<<<1, 128>>>();
    k_scan_add<<<grid_nodes, 256>>>();
    k_scatter<<<grid_half, 256>>>(ei_src2, ei_dst2);

    // GAT layers
    k_gemm1<<<grid_gemm1, 256>>>((const float4*)x, W1, as1, ad1);
    k_gather1<<<grid_nodes, 256>>>(b1, W2, as2, ad2);
    k_gather2<<<grid_nodes, 256>>>(b2, Wlin, blin, out);
}